// round 9
// baseline (speedup 1.0000x reference)
#include <cuda_runtime.h>
#include <math.h>

// Problem constants (fixed by reference setup_inputs)
#define N_BATCH 256
#define M_ROWS  8
#define T_LEN   16384
#define NPAIRS  36          // 8*9/2 lower-tri (symmetric Gram)
#define THREADS 512
#define NWARPS  (THREADS / 32)
#define T4      (T_LEN / 4)              // 4096 float4 per row
#define SPLITS  4                        // units per batch
#define UNIT_T4 (T4 / SPLITS)            // 1024 float4 columns per unit
#define TOTAL_UNITS (N_BATCH * SPLITS)   // 1024

// Cross-CTA scratch (static device globals; no allocation)
__device__ float        g_part[N_BATCH * SPLITS * NPAIRS];
__device__ unsigned int g_cnt[N_BATCH];   // zero-init; reset by finalizer

__device__ __forceinline__ int cidx(int a, int b) {
    const int m = a > b ? a : b;
    const int k = a > b ? b : a;
    return m * (m + 1) / 2 + k;
}

// Flush the CTA's accumulated partial for batch n covering splits [sa..se];
// the CTA that completes the batch finalizes it (deterministic order).
__device__ __forceinline__ void flush_batch(
    int n, int sa, int se, float* acc, float* __restrict__ out,
    float (*sred)[NPAIRS], float* sC, int* s_fin, int tid)
{
    const int warp = tid >> 5;
    const int lane = tid & 31;

#pragma unroll
    for (int i = 0; i < NPAIRS; i++) {
#pragma unroll
        for (int off = 16; off > 0; off >>= 1)
            acc[i] += __shfl_down_sync(0xffffffffu, acc[i], off);
    }
    if (lane == 0) {
#pragma unroll
        for (int i = 0; i < NPAIRS; i++) sred[warp][i] = acc[i];
    }
    __syncthreads();

    if (tid < NPAIRS) {
        float s = 0.f;
#pragma unroll
        for (int w = 0; w < NWARPS; w++) s += sred[w][tid];
        // scaled partial; merged run stored in slot sa, covered slots zeroed
        g_part[(n * SPLITS + sa) * NPAIRS + tid] = s * (1.0f / (float)T_LEN);
        for (int z = sa + 1; z <= se; z++)
            g_part[(n * SPLITS + z) * NPAIRS + tid] = 0.f;
        __threadfence();
    }
    __syncthreads();

    if (tid == 0) {
        const unsigned int add = (unsigned int)(se - sa + 1);
        const unsigned int old = atomicAdd(&g_cnt[n], add);
        *s_fin = (old + add == SPLITS) ? 1 : 0;
    }
    __syncthreads();

    if (*s_fin) {
        if (tid < NPAIRS) {
            float s = 0.f;
#pragma unroll
            for (int sp = 0; sp < SPLITS; sp++) {
                const volatile float* p =
                    (const volatile float*)&g_part[(n * SPLITS + sp) * NPAIRS + tid];
                s += *p;
            }
            sC[tid] = s;   // C entries (already /T)
        }
        __syncthreads();

        if (tid == 0) {
            // R[s1][s2] = mean_j C[j+s1][j+s2]; triu_indices(5) row-major.
            float tri[15];
            int p = 0;
#pragma unroll
            for (int s1 = 0; s1 < 5; s1++) {
#pragma unroll
                for (int s2 = s1; s2 < 5; s2++) {
                    float r = 0.f;
#pragma unroll
                    for (int j = 0; j < 4; j++)
                        r += sC[cidx(j + s1, j + s2)];
                    tri[p++] = r * 0.25f;
                }
            }
            float mean = 0.f;
#pragma unroll
            for (int i = 0; i < 15; i++) mean += tri[i];
            mean *= (1.0f / 30.0f);

            float var = 0.f;
#pragma unroll
            for (int i = 0; i < 15; i++) {
                const float d = tri[i] - mean;
                var += d * d;
            }
            var += 15.0f * mean * mean;   // 15 zero features contribute mean^2
            var *= (1.0f / 30.0f);

            const float inv = 1.0f / (sqrtf(var) + 1e-8f);
            float* o = out + n * 30;
#pragma unroll
            for (int i = 0; i < 15; i++) o[i] = (tri[i] - mean) * inv;
            const float zval = -mean * inv;
#pragma unroll
            for (int i = 15; i < 30; i++) o[i] = zval;

            atomicExch(&g_cnt[n], 0u);   // reset for next graph replay
        }
        __syncthreads();
    }
}

__global__ void __launch_bounds__(THREADS)
ssf_persistent_kernel(const float* __restrict__ X, float* __restrict__ out) {
    __shared__ float sred[NWARPS][NPAIRS];
    __shared__ float sC[NPAIRS];
    __shared__ int   s_fin;

    const int tid = threadIdx.x;
    const int G   = gridDim.x;
    const int u0  = (int)(((long long)blockIdx.x * TOTAL_UNITS) / G);
    const int u1  = (int)(((long long)(blockIdx.x + 1) * TOTAL_UNITS) / G);
    if (u0 >= u1) return;

    const float4* __restrict__ X4 = reinterpret_cast<const float4*>(X);

    float acc[NPAIRS];
#pragma unroll
    for (int i = 0; i < NPAIRS; i++) acc[i] = 0.f;

    int run_n  = u0 >> 2;
    int run_sa = u0 & 3;

#pragma unroll 1
    for (int u = u0; u < u1; u++) {
        const int n = u >> 2;
        const int s = u & 3;

        if (n != run_n) {
            // batch changes only after split 3 completed
            flush_batch(run_n, run_sa, 3, acc, out, sred, sC, &s_fin, tid);
            run_n = n;
            run_sa = 0;
#pragma unroll
            for (int i = 0; i < NPAIRS; i++) acc[i] = 0.f;
        }

        // ---- R8 inner body: 16 back-to-back LDG.128, then 288 FMAs ----
        const float4* __restrict__ base = X4 + (size_t)n * M_ROWS * T4;
        const int t4a = s * UNIT_T4 + tid;
        const int t4b = t4a + THREADS;

        float4 va[M_ROWS], vb[M_ROWS];
#pragma unroll
        for (int m = 0; m < M_ROWS; m++)
            va[m] = base[m * T4 + t4a];
#pragma unroll
        for (int m = 0; m < M_ROWS; m++)
            vb[m] = base[m * T4 + t4b];

        int idx = 0;
#pragma unroll
        for (int m = 0; m < M_ROWS; m++) {
#pragma unroll
            for (int k = 0; k <= m; k++) {
                acc[idx] = fmaf(va[m].x, va[k].x, acc[idx]);
                acc[idx] = fmaf(va[m].y, va[k].y, acc[idx]);
                acc[idx] = fmaf(va[m].z, va[k].z, acc[idx]);
                acc[idx] = fmaf(va[m].w, va[k].w, acc[idx]);
                acc[idx] = fmaf(vb[m].x, vb[k].x, acc[idx]);
                acc[idx] = fmaf(vb[m].y, vb[k].y, acc[idx]);
                acc[idx] = fmaf(vb[m].z, vb[k].z, acc[idx]);
                acc[idx] = fmaf(vb[m].w, vb[k].w, acc[idx]);
                idx++;
            }
        }
    }

    flush_batch(run_n, run_sa, (u1 - 1) & 3, acc, out, sred, sC, &s_fin, tid);
}

extern "C" void kernel_launch(void* const* d_in, const int* in_sizes, int n_in,
                              void* d_out, int out_size) {
    const float* X = (const float*)d_in[0];
    float* out = (float*)d_out;

    int sm_count = 148;
    cudaDeviceGetAttribute(&sm_count, cudaDevAttrMultiProcessorCount, 0);
    if (sm_count < 1) sm_count = 148;
    if (sm_count > TOTAL_UNITS) sm_count = TOTAL_UNITS;

    ssf_persistent_kernel<<<sm_count, THREADS>>>(X, out);
}

// round 10
// speedup vs baseline: 1.1318x; 1.1318x over previous
#include <cuda_runtime.h>
#include <math.h>

// Problem constants (fixed by reference setup_inputs)
#define N_BATCH 256
#define M_ROWS  8
#define T_LEN   16384
#define NPAIRS  36          // 8*9/2 lower-tri (symmetric Gram)
#define THREADS 512
#define NWARPS  (THREADS / 32)
#define T4      (T_LEN / 4)              // 4096 float4 per row
#define CHUNKS  2                        // time-chunks per outer iteration
#define ITERS   (T4 / (THREADS * CHUNKS))  // 4

__device__ __forceinline__ int cidx(int a, int b) {
    const int m = a > b ? a : b;
    const int k = a > b ? b : a;
    return m * (m + 1) / 2 + k;
}

__device__ __forceinline__ void l2_prefetch(const void* p) {
    asm volatile("prefetch.global.L2 [%0];" :: "l"(p));
}

__global__ void __launch_bounds__(THREADS)
ssf_fused_kernel(const float* __restrict__ X, float* __restrict__ out) {
    const int n   = blockIdx.x;
    const int tid = threadIdx.x;

    const float4* __restrict__ base =
        reinterpret_cast<const float4*>(X + (size_t)n * M_ROWS * T_LEN);

    float acc[NPAIRS];
#pragma unroll
    for (int i = 0; i < NPAIRS; i++) acc[i] = 0.f;

#pragma unroll
    for (int it = 0; it < ITERS; it++) {
        const int t4a = tid + it * (THREADS * CHUNKS);
        const int t4b = t4a + THREADS;

        // 16 LDG.128 issued back-to-back (R8-proven)
        float4 va[M_ROWS], vb[M_ROWS];
#pragma unroll
        for (int m = 0; m < M_ROWS; m++)
            va[m] = base[m * T4 + t4a];
#pragma unroll
        for (int m = 0; m < M_ROWS; m++)
            vb[m] = base[m * T4 + t4b];

        // L2 prefetch next iteration's lines: no regs, no scoreboard,
        // cuts demand latency 577 -> ~250 cyc for the next round.
        if (it + 1 < ITERS) {
            const int pa = t4a + THREADS * CHUNKS;
            const int pb = t4b + THREADS * CHUNKS;
#pragma unroll
            for (int m = 0; m < M_ROWS; m++)
                l2_prefetch(base + m * T4 + pa);
#pragma unroll
            for (int m = 0; m < M_ROWS; m++)
                l2_prefetch(base + m * T4 + pb);
        }

        int idx = 0;
#pragma unroll
        for (int m = 0; m < M_ROWS; m++) {
#pragma unroll
            for (int k = 0; k <= m; k++) {
                acc[idx] = fmaf(va[m].x, va[k].x, acc[idx]);
                acc[idx] = fmaf(va[m].y, va[k].y, acc[idx]);
                acc[idx] = fmaf(va[m].z, va[k].z, acc[idx]);
                acc[idx] = fmaf(va[m].w, va[k].w, acc[idx]);
                acc[idx] = fmaf(vb[m].x, vb[k].x, acc[idx]);
                acc[idx] = fmaf(vb[m].y, vb[k].y, acc[idx]);
                acc[idx] = fmaf(vb[m].z, vb[k].z, acc[idx]);
                acc[idx] = fmaf(vb[m].w, vb[k].w, acc[idx]);
                idx++;
            }
        }
    }

    // Intra-warp tree reduce for each of the 36 sums
#pragma unroll
    for (int i = 0; i < NPAIRS; i++) {
#pragma unroll
        for (int off = 16; off > 0; off >>= 1)
            acc[i] += __shfl_down_sync(0xffffffffu, acc[i], off);
    }

    __shared__ float sred[NWARPS][NPAIRS];
    __shared__ float sC[NPAIRS];
    const int warp = tid >> 5;
    const int lane = tid & 31;
    if (lane == 0) {
#pragma unroll
        for (int i = 0; i < NPAIRS; i++) sred[warp][i] = acc[i];
    }
    __syncthreads();

    if (tid < NPAIRS) {
        float s = 0.f;
#pragma unroll
        for (int w = 0; w < NWARPS; w++) s += sred[w][tid];
        sC[tid] = s * (1.0f / (float)T_LEN);   // C = Gram / T
    }
    __syncthreads();

    if (tid == 0) {
        // R[s1][s2] = mean over j of C[j+s1][j+s2]; upper triangle in
        // jnp.triu_indices(5) (row-major) order.
        float tri[15];
        int p = 0;
#pragma unroll
        for (int s1 = 0; s1 < 5; s1++) {
#pragma unroll
            for (int s2 = s1; s2 < 5; s2++) {
                float r = 0.f;
#pragma unroll
                for (int j = 0; j < 4; j++)
                    r += sC[cidx(j + s1, j + s2)];
                tri[p++] = r * 0.25f;
            }
        }

        // feat = [tri (15), zeros (15)]; standardize over all 30 (pop. std)
        float mean = 0.f;
#pragma unroll
        for (int i = 0; i < 15; i++) mean += tri[i];
        mean *= (1.0f / 30.0f);

        float var = 0.f;
#pragma unroll
        for (int i = 0; i < 15; i++) {
            const float d = tri[i] - mean;
            var += d * d;
        }
        var += 15.0f * mean * mean;   // 15 zero entries each contribute mean^2
        var *= (1.0f / 30.0f);

        const float inv = 1.0f / (sqrtf(var) + 1e-8f);

        float* o = out + n * 30;
#pragma unroll
        for (int i = 0; i < 15; i++) o[i] = (tri[i] - mean) * inv;
        const float zval = -mean * inv;
#pragma unroll
        for (int i = 15; i < 30; i++) o[i] = zval;
    }
}

extern "C" void kernel_launch(void* const* d_in, const int* in_sizes, int n_in,
                              void* d_out, int out_size) {
    const float* X = (const float*)d_in[0];
    float* out = (float*)d_out;
    ssf_fused_kernel<<<N_BATCH, THREADS>>>(X, out);
}